// round 1
// baseline (speedup 1.0000x reference)
#include <cuda_runtime.h>
#include <math.h>

// ESN: B=256, T=512, D=64, N=512, leak=0.5
// Output layout assumed: [ X (B,T,N) fp32 ][ X_last (B,N) fp32 ]

#define BB 256
#define TT 512
#define DD 64
#define NN 512
#define LEAK 0.5f

typedef unsigned long long ull;

__device__ __forceinline__ void fma2(ull &acc, ull a, ull b) {
    asm("fma.rn.f32x2 %0, %1, %2, %0;" : "+l"(acc) : "l"(a), "l"(b));
}
__device__ __forceinline__ float2 unpack2(ull v) {
    float2 r; asm("mov.b64 {%0, %1}, %2;" : "=f"(r.x), "=f"(r.y) : "l"(v)); return r;
}

// ---------------------------------------------------------------------------
// Projection: U[row, n] = inputs[row, :] @ W_in[:, n] + b_in[n]
// rows = B*T (row = b*T + t). For t==0 rows, apply x0 = leak * tanh(U).
// Tile 32(M) x 32(N), K=64 in one shot. 128 threads.
// ---------------------------------------------------------------------------
__global__ __launch_bounds__(128) void proj_kernel(
    const float* __restrict__ inp, const float* __restrict__ Win,
    const float* __restrict__ bin, float* __restrict__ X)
{
    __shared__ __align__(16) float As[DD][36];   // [k][m], padded
    __shared__ __align__(16) float Wd[DD][64];   // [k][2n] duplicated pairs

    const int tid = threadIdx.x;
    const int m0 = blockIdx.x * 32;
    const int n0 = blockIdx.y * 32;

    // Load A tile: 32 rows x 64 cols (transposed into SMEM)
    {
        int c = tid & 63, mi = tid >> 6;     // c: 0..63, mi: 0..1
        #pragma unroll
        for (int j = 0; j < 16; j++) {
            int m = j * 2 + mi;
            As[c][m] = inp[(m0 + m) * DD + c];
        }
    }
    // Load W tile duplicated: Wd[k][2n] = Wd[k][2n+1] = W_in[k][n0+n]
    {
        int n = tid & 31, kw = tid >> 5;     // n: 0..31, kw: 0..3
        #pragma unroll
        for (int j = 0; j < 16; j++) {
            int k = j * 4 + kw;
            float w = Win[k * NN + n0 + n];
            Wd[k][2 * n] = w; Wd[k][2 * n + 1] = w;
        }
    }
    __syncthreads();

    const int tx = tid & 7;        // col group: cols 4tx..4tx+3
    const int ty = tid >> 3;       // row pair:  rows 2ty, 2ty+1
    ull acc0 = 0, acc1 = 0, acc2 = 0, acc3 = 0;

    #pragma unroll
    for (int k = 0; k < DD; k++) {
        ull a = *(const ull*)&As[k][2 * ty];
        const ulonglong2* bp = (const ulonglong2*)&Wd[k][8 * tx];
        ulonglong2 b01 = bp[0], b23 = bp[1];
        fma2(acc0, a, b01.x); fma2(acc1, a, b01.y);
        fma2(acc2, a, b23.x); fma2(acc3, a, b23.y);
    }

    const int r0 = m0 + 2 * ty;           // row0 (even), row1 = r0+1
    const int t0 = r0 & (TT - 1);         // time of row0 (even); row1 time >= 1
    const int nb = n0 + 4 * tx;
    ull accs[4] = {acc0, acc1, acc2, acc3};
    #pragma unroll
    for (int c = 0; c < 4; c++) {
        float2 v = unpack2(accs[c]);
        int n = nb + c;
        float b = bin[n];
        float u0 = v.x + b;
        float u1 = v.y + b;
        X[(size_t)r0 * NN + n]       = (t0 == 0) ? (LEAK * tanhf(u0)) : u0;
        X[(size_t)(r0 + 1) * NN + n] = u1;   // time t0+1 >= 1 always
    }
}

// ---------------------------------------------------------------------------
// Recurrence step t (t in 1..T-1), in place on X:
//   X[:, t, :] = (1-a)*X[:, t-1, :] + a*tanh( X[:, t, :](=U_t) + X[:, t-1, :]@W_res + b_res )
// GEMM M=256(batch), N=512, K=512. Tile 32x32 -> 8x16 = 128 CTAs.
// Double-buffered SMEM, single sync per chunk, f32x2 inner loop.
// ---------------------------------------------------------------------------
__global__ __launch_bounds__(128) void step_kernel(
    float* __restrict__ X, const float* __restrict__ Wres,
    const float* __restrict__ bres, int t)
{
    __shared__ __align__(16) float Xs[2][32][36];   // [buf][k][m]
    __shared__ __align__(16) float Wd[2][32][64];   // [buf][k][2n] duplicated

    const int tid = threadIdx.x;
    const int m0 = blockIdx.x * 32;    // batch rows
    const int n0 = blockIdx.y * 32;
    const int TN = TT * NN;

    const float* __restrict__ Xp = X + (size_t)(t - 1) * NN;  // x_prev base (per-batch stride TN)

    const int ka = tid & 31, mi = tid >> 5;   // A loader
    const int nw = tid & 31, kw = tid >> 5;   // W loader

    float ra[8], rw[8];
    // Prefetch chunk 0
    #pragma unroll
    for (int j = 0; j < 8; j++) {
        int m = j * 4 + mi;
        ra[j] = Xp[(size_t)(m0 + m) * TN + ka];
        int k = j * 4 + kw;
        rw[j] = Wres[k * NN + n0 + nw];
    }

    const int tx = tid & 7;
    const int ty = tid >> 3;
    ull acc0 = 0, acc1 = 0, acc2 = 0, acc3 = 0;

    for (int ch = 0; ch < 16; ch++) {
        const int buf = ch & 1;
        // Store current chunk regs -> SMEM[buf]
        #pragma unroll
        for (int j = 0; j < 8; j++) {
            int m = j * 4 + mi;
            Xs[buf][ka][m] = ra[j];
            int k = j * 4 + kw;
            Wd[buf][k][2 * nw] = rw[j]; Wd[buf][k][2 * nw + 1] = rw[j];
        }
        __syncthreads();
        // Prefetch next chunk into regs (overlaps with compute below)
        if (ch < 15) {
            int kc = (ch + 1) * 32;
            #pragma unroll
            for (int j = 0; j < 8; j++) {
                int m = j * 4 + mi;
                ra[j] = Xp[(size_t)(m0 + m) * TN + kc + ka];
                int k = j * 4 + kw;
                rw[j] = Wres[(kc + k) * NN + n0 + nw];
            }
        }
        // Compute on SMEM[buf]
        #pragma unroll
        for (int k = 0; k < 32; k++) {
            ull a = *(const ull*)&Xs[buf][k][2 * ty];
            const ulonglong2* bp = (const ulonglong2*)&Wd[buf][k][8 * tx];
            ulonglong2 b01 = bp[0], b23 = bp[1];
            fma2(acc0, a, b01.x); fma2(acc1, a, b01.y);
            fma2(acc2, a, b23.x); fma2(acc3, a, b23.y);
        }
    }

    // Epilogue: leaky tanh update, in place
    const int b0 = m0 + 2 * ty;        // batch rows b0, b0+1
    const int nb = n0 + 4 * tx;
    ull accs[4] = {acc0, acc1, acc2, acc3};
    #pragma unroll
    for (int c = 0; c < 4; c++) {
        float2 s = unpack2(accs[c]);
        int n = nb + c;
        float br = bres[n];
        size_t i0 = (size_t)b0 * TN + (size_t)t * NN + n;
        float u0 = X[i0], xp0 = X[i0 - NN];
        X[i0] = (1.0f - LEAK) * xp0 + LEAK * tanhf(u0 + s.x + br);
        size_t i1 = i0 + (size_t)TN;
        float u1 = X[i1], xp1 = X[i1 - NN];
        X[i1] = (1.0f - LEAK) * xp1 + LEAK * tanhf(u1 + s.y + br);
    }
}

// ---------------------------------------------------------------------------
// Tail: copy X[:, T-1, :] into the X_last output region
// ---------------------------------------------------------------------------
__global__ void tail_kernel(const float* __restrict__ X, float* __restrict__ out_last)
{
    int i = blockIdx.x * blockDim.x + threadIdx.x;
    if (i < BB * NN) {
        int b = i >> 9;         // /512
        int n = i & 511;
        out_last[i] = X[(size_t)b * TT * NN + (size_t)(TT - 1) * NN + n];
    }
}

extern "C" void kernel_launch(void* const* d_in, const int* in_sizes, int n_in,
                              void* d_out, int out_size)
{
    const float* inp  = (const float*)d_in[0];
    const float* Win  = (const float*)d_in[1];
    const float* bin  = (const float*)d_in[2];
    const float* Wres = (const float*)d_in[3];
    const float* bres = (const float*)d_in[4];

    float* X = (float*)d_out;                       // (B, T, N)
    float* xlast = X + (size_t)BB * TT * NN;        // (B, N)

    dim3 g1(BB * TT / 32, NN / 32);                 // 4096 x 16
    proj_kernel<<<g1, 128>>>(inp, Win, bin, X);

    dim3 g2(BB / 32, NN / 32);                      // 8 x 16 = 128 CTAs
    for (int t = 1; t < TT; t++)
        step_kernel<<<g2, 128>>>(X, Wres, bres, t);

    tail_kernel<<<(BB * NN + 255) / 256, 256>>>(X, xlast);
}

// round 2
// speedup vs baseline: 1.9276x; 1.9276x over previous
#include <cuda_runtime.h>
#include <math.h>

// ESN: B=256, T=512, D=64, N=512, leak=0.5
// Output: [ X (B,T,N) fp32 ][ X_last (B,N) fp32 ]

#define BB 256
#define TT 512
#define DD 64
#define NN 512
#define LEAK 0.5f
#define NCTA 128
#define RK 66   // Xsd row stride in words (per k): 64 + 2 pad -> conflict-free

typedef unsigned long long ull;

__device__ unsigned g_count;

__device__ __forceinline__ void fma2(ull &acc, ull a, ull b) {
    asm("fma.rn.f32x2 %0, %1, %2, %0;" : "+l"(acc) : "l"(a), "l"(b));
}
__device__ __forceinline__ float2 unpack2(ull v) {
    float2 r; asm("mov.b64 {%0, %1}, %2;" : "=f"(r.x), "=f"(r.y) : "l"(v)); return r;
}

__global__ void init_kernel() { g_count = 0u; }

// ---------------------------------------------------------------------------
// Projection: U[row, n] = inputs[row, :] @ W_in[:, n] + b_in[n]; x0 for t==0.
// ---------------------------------------------------------------------------
__global__ __launch_bounds__(128) void proj_kernel(
    const float* __restrict__ inp, const float* __restrict__ Win,
    const float* __restrict__ bin, float* __restrict__ X)
{
    __shared__ __align__(16) float As[DD][36];
    __shared__ __align__(16) float Wd[DD][64];

    const int tid = threadIdx.x;
    const int m0 = blockIdx.x * 32;
    const int n0 = blockIdx.y * 32;

    {
        int c = tid & 63, mi = tid >> 6;
        #pragma unroll
        for (int j = 0; j < 16; j++) {
            int m = j * 2 + mi;
            As[c][m] = inp[(m0 + m) * DD + c];
        }
    }
    {
        int n = tid & 31, kw = tid >> 5;
        #pragma unroll
        for (int j = 0; j < 16; j++) {
            int k = j * 4 + kw;
            float w = Win[k * NN + n0 + n];
            Wd[k][2 * n] = w; Wd[k][2 * n + 1] = w;
        }
    }
    __syncthreads();

    const int tx = tid & 7;
    const int ty = tid >> 3;
    ull acc0 = 0, acc1 = 0, acc2 = 0, acc3 = 0;

    #pragma unroll
    for (int k = 0; k < DD; k++) {
        ull a = *(const ull*)&As[k][2 * ty];
        const ulonglong2* bp = (const ulonglong2*)&Wd[k][8 * tx];
        ulonglong2 b01 = bp[0], b23 = bp[1];
        fma2(acc0, a, b01.x); fma2(acc1, a, b01.y);
        fma2(acc2, a, b23.x); fma2(acc3, a, b23.y);
    }

    const int r0 = m0 + 2 * ty;
    const int t0 = r0 & (TT - 1);
    const int nb = n0 + 4 * tx;
    ull accs[4] = {acc0, acc1, acc2, acc3};
    #pragma unroll
    for (int c = 0; c < 4; c++) {
        float2 v = unpack2(accs[c]);
        int n = nb + c;
        float b = bin[n];
        float u0 = v.x + b;
        float u1 = v.y + b;
        X[(size_t)r0 * NN + n]       = (t0 == 0) ? (LEAK * tanhf(u0)) : u0;
        X[(size_t)(r0 + 1) * NN + n] = u1;
    }
}

// ---------------------------------------------------------------------------
// Persistent recurrence kernel: 128 CTAs (8 m-tiles x 16 n-tiles), 128 thr.
// W slab (512x32) resident in SMEM for all steps. Per step: stage x_prev slab
// (32x512) as duplicated f32x2 pairs, GEMM, leaky-tanh epilogue, grid barrier.
// ---------------------------------------------------------------------------
__global__ __launch_bounds__(128, 1) void esn_persist(
    float* __restrict__ X, const float* __restrict__ Wres,
    const float* __restrict__ bres, float* __restrict__ xlast)
{
    extern __shared__ __align__(16) float smem[];
    float* Xsd = smem;               // [512][RK]: pair (x,x) at word [k*RK + 2m]
    float* Ws  = smem + NN * RK;     // [512][32]

    const int tid = threadIdx.x;
    const int bx  = blockIdx.x;
    const int m0 = (bx & 7) * 32;    // batch-row tile
    const int n0 = (bx >> 3) * 32;   // output-col tile
    const int TN = TT * NN;

    // Stage W slab once (coalesced LDG.32, conflict-free STS)
    {
        const int n = tid & 31;
        for (int k = tid >> 5; k < NN; k += 4)
            Ws[k * 32 + n] = Wres[k * NN + n0 + n];
    }

    const int tx = tid & 7;          // 4 output cols: n0+4tx..+3
    const int ty = tid >> 3;         // 2 output rows: m0+2ty, +1
    const int sr = tid >> 2;         // staging row 0..31
    const int sq = tid & 3;          // staging quarter

    const float4 br4 = *(const float4*)&bres[n0 + 4 * tx];

    for (int t = 1; t < TT; t++) {
        // ---- stage x_prev slab, duplicated pairs, L2-coherent loads ----
        const float4* xs = (const float4*)(X + (size_t)(m0 + sr) * TN + (size_t)(t - 1) * NN);
        float* xd = Xsd + 2 * sr;
        #pragma unroll 8
        for (int j = 0; j < 32; j++) {
            int k4 = sq + 4 * j;
            float4 v = __ldcg(xs + k4);
            int k = 4 * k4;
            *(float2*)(xd + (size_t)(k + 0) * RK) = make_float2(v.x, v.x);
            *(float2*)(xd + (size_t)(k + 1) * RK) = make_float2(v.y, v.y);
            *(float2*)(xd + (size_t)(k + 2) * RK) = make_float2(v.z, v.z);
            *(float2*)(xd + (size_t)(k + 3) * RK) = make_float2(v.w, v.w);
        }
        __syncthreads();

        // ---- GEMM: 512-k loop, f32x2, FMA-pipe bound ----
        ull a00 = 0, a01 = 0, a10 = 0, a11 = 0;
        const float* xr0 = Xsd + 4 * ty;       // m = 2ty   -> word 2m = 4ty
        const float* xr1 = Xsd + 4 * ty + 2;   // m = 2ty+1
        const float* wp  = Ws + 4 * tx;
        #pragma unroll 16
        for (int k = 0; k < NN; k++) {
            ull am0 = *(const ull*)(xr0 + k * RK);
            ull am1 = *(const ull*)(xr1 + k * RK);
            ulonglong2 b = *(const ulonglong2*)(wp + k * 32);
            fma2(a00, am0, b.x); fma2(a01, am0, b.y);
            fma2(a10, am1, b.x); fma2(a11, am1, b.y);
        }

        // ---- epilogue: x_t = 0.5*x_prev + 0.5*tanh(U + s + b_res) ----
        const int r0 = m0 + 2 * ty;
        size_t base = (size_t)r0 * TN + (size_t)t * NN + n0 + 4 * tx;
        float2 s0 = unpack2(a00), s1 = unpack2(a01);
        float2 s2 = unpack2(a10), s3 = unpack2(a11);
        float4 u0 = *(const float4*)&X[base];
        float4 u1 = *(const float4*)&X[base + TN];
        const float* xp0 = Xsd + (size_t)(n0 + 4 * tx) * RK + 4 * ty;      // m=2ty
        const float* xp1 = xp0 + 2;                                        // m=2ty+1

        float4 o0, o1;
        o0.x = 0.5f * xp0[0 * RK] + 0.5f * tanhf(u0.x + s0.x + br4.x);
        o0.y = 0.5f * xp0[1 * RK] + 0.5f * tanhf(u0.y + s0.y + br4.y);
        o0.z = 0.5f * xp0[2 * RK] + 0.5f * tanhf(u0.z + s1.x + br4.z);
        o0.w = 0.5f * xp0[3 * RK] + 0.5f * tanhf(u0.w + s1.y + br4.w);
        o1.x = 0.5f * xp1[0 * RK] + 0.5f * tanhf(u1.x + s2.x + br4.x);
        o1.y = 0.5f * xp1[1 * RK] + 0.5f * tanhf(u1.y + s2.y + br4.y);
        o1.z = 0.5f * xp1[2 * RK] + 0.5f * tanhf(u1.z + s3.x + br4.z);
        o1.w = 0.5f * xp1[3 * RK] + 0.5f * tanhf(u1.w + s3.y + br4.w);

        *(float4*)&X[base]      = o0;
        *(float4*)&X[base + TN] = o1;
        if (t == TT - 1) {
            *(float4*)&xlast[(size_t)r0 * NN + n0 + 4 * tx]       = o0;
            *(float4*)&xlast[(size_t)(r0 + 1) * NN + n0 + 4 * tx] = o1;
        }

        // ---- grid barrier (skip after last step) ----
        if (t < TT - 1) {
            __threadfence();        // make this thread's STGs visible GPU-wide
            __syncthreads();        // all threads' fences done before arrive
            if (tid == 0) {
                atomicAdd(&g_count, 1u);
                unsigned target = (unsigned)t * NCTA;
                while (*(volatile unsigned*)&g_count < target) { }
            }
            __syncthreads();
        }
    }
}

extern "C" void kernel_launch(void* const* d_in, const int* in_sizes, int n_in,
                              void* d_out, int out_size)
{
    const float* inp  = (const float*)d_in[0];
    const float* Win  = (const float*)d_in[1];
    const float* bin  = (const float*)d_in[2];
    const float* Wres = (const float*)d_in[3];
    const float* bres = (const float*)d_in[4];

    float* X = (float*)d_out;                       // (B, T, N)
    float* xlast = X + (size_t)BB * TT * NN;        // (B, N)

    const int smem_bytes = (NN * RK + NN * 32) * sizeof(float);  // 200704
    cudaFuncSetAttribute(esn_persist, cudaFuncAttributeMaxDynamicSharedMemorySize, smem_bytes);

    dim3 g1(BB * TT / 32, NN / 32);
    proj_kernel<<<g1, 128>>>(inp, Win, bin, X);

    init_kernel<<<1, 1>>>();

    esn_persist<<<NCTA, 128, smem_bytes>>>(X, Wres, bres, xlast);
}

// round 3
// speedup vs baseline: 1.9735x; 1.0238x over previous
#include <cuda_runtime.h>
#include <math.h>

// ESN: B=256, T=512, D=64, N=512, leak=0.5
// Output: [ X (B,T,N) fp32 ][ X_last (B,N) fp32 ]

#define BB 256
#define TT 512
#define DD 64
#define NN 512
#define LEAK 0.5f
#define NCTA 128
#define RK 68          // Xsd row stride in words: 16B-aligned rows, 4-bank skew
#define NGRP 8         // one barrier group per m-slab
#define GRP_SZ 16      // CTAs per group (all n-tiles of one m-slab)

typedef unsigned long long ull;

__device__ unsigned g_cnt[NGRP * 32];   // 128B-spaced counters

__device__ __forceinline__ void fma2(ull &acc, ull a, ull b) {
    asm("fma.rn.f32x2 %0, %1, %2, %0;" : "+l"(acc) : "l"(a), "l"(b));
}
__device__ __forceinline__ float2 unpack2(ull v) {
    float2 r; asm("mov.b64 {%0, %1}, %2;" : "=f"(r.x), "=f"(r.y) : "l"(v)); return r;
}
__device__ __forceinline__ unsigned atom_add_rel(unsigned* p, unsigned v) {
    unsigned r;
    asm volatile("atom.add.release.gpu.global.u32 %0, [%1], %2;"
                 : "=r"(r) : "l"(p), "r"(v) : "memory");
    return r;
}
__device__ __forceinline__ unsigned ld_acq(const unsigned* p) {
    unsigned r;
    asm volatile("ld.acquire.gpu.global.u32 %0, [%1];" : "=r"(r) : "l"(p) : "memory");
    return r;
}

__global__ void init_kernel() {
    if (threadIdx.x < NGRP) g_cnt[threadIdx.x * 32] = 0u;
}

// ---------------------------------------------------------------------------
// Projection: U[row, n] = inputs[row, :] @ W_in[:, n] + b_in[n]; x0 for t==0.
// ---------------------------------------------------------------------------
__global__ __launch_bounds__(128) void proj_kernel(
    const float* __restrict__ inp, const float* __restrict__ Win,
    const float* __restrict__ bin, float* __restrict__ X)
{
    __shared__ __align__(16) float As[DD][36];
    __shared__ __align__(16) float Wd[DD][64];

    const int tid = threadIdx.x;
    const int m0 = blockIdx.x * 32;
    const int n0 = blockIdx.y * 32;

    {
        int c = tid & 63, mi = tid >> 6;
        #pragma unroll
        for (int j = 0; j < 16; j++) {
            int m = j * 2 + mi;
            As[c][m] = inp[(m0 + m) * DD + c];
        }
    }
    {
        int n = tid & 31, kw = tid >> 5;
        #pragma unroll
        for (int j = 0; j < 16; j++) {
            int k = j * 4 + kw;
            float w = Win[k * NN + n0 + n];
            Wd[k][2 * n] = w; Wd[k][2 * n + 1] = w;
        }
    }
    __syncthreads();

    const int tx = tid & 7;
    const int ty = tid >> 3;
    ull acc0 = 0, acc1 = 0, acc2 = 0, acc3 = 0;

    #pragma unroll
    for (int k = 0; k < DD; k++) {
        ull a = *(const ull*)&As[k][2 * ty];
        const ulonglong2* bp = (const ulonglong2*)&Wd[k][8 * tx];
        ulonglong2 b01 = bp[0], b23 = bp[1];
        fma2(acc0, a, b01.x); fma2(acc1, a, b01.y);
        fma2(acc2, a, b23.x); fma2(acc3, a, b23.y);
    }

    const int r0 = m0 + 2 * ty;
    const int t0 = r0 & (TT - 1);
    const int nb = n0 + 4 * tx;
    ull accs[4] = {acc0, acc1, acc2, acc3};
    #pragma unroll
    for (int c = 0; c < 4; c++) {
        float2 v = unpack2(accs[c]);
        int n = nb + c;
        float b = bin[n];
        float u0 = v.x + b;
        float u1 = v.y + b;
        X[(size_t)r0 * NN + n]       = (t0 == 0) ? (LEAK * tanhf(u0)) : u0;
        X[(size_t)(r0 + 1) * NN + n] = u1;
    }
}

// ---------------------------------------------------------------------------
// Persistent recurrence: 128 CTAs = 8 m-slabs x 16 n-tiles, 128 threads.
// W slab resident in SMEM; per-step: stage x_prev slab (duplicated pairs),
// warp-tiled 16x16 GEMM, leaky-tanh epilogue, 16-CTA group barrier.
// ---------------------------------------------------------------------------
__global__ __launch_bounds__(128, 1) void esn_persist(
    float* __restrict__ X, const float* __restrict__ Wres,
    const float* __restrict__ bres, float* __restrict__ xlast)
{
    extern __shared__ __align__(16) float smem[];
    float* Xsd = smem;               // [512][RK]: pair (x,x) at word [k*RK + 2m]
    float* Ws  = smem + NN * RK;     // [512][32]

    const int tid = threadIdx.x;
    const int bx  = blockIdx.x;
    const int grp = bx & 7;          // m-slab group
    const int m0 = grp * 32;
    const int n0 = (bx >> 3) * 32;
    const int TN = TT * NN;
    unsigned* cnt = &g_cnt[grp * 32];

    // Stage W slab once
    {
        const int n = tid & 31;
        for (int k = tid >> 5; k < NN; k += 4)
            Ws[k * 32 + n] = Wres[k * NN + n0 + n];
    }

    // warp-tile mapping: warp w -> 16x16 tile (wm = w&1 rows, wn = w>>1 cols)
    const int w  = tid >> 5, l = tid & 31;
    const int wm = w & 1, wn = w >> 1;
    const int q  = l >> 2;           // row pair within warp-tile: rows 2q,2q+1
    const int c4 = (l & 3) * 4;      // col quad within warp-tile
    const int mloc = 16 * wm + 2 * q;        // local row (even)
    const int nloc = 16 * wn + c4;           // local col (quad base)

    const int sr = tid >> 2;         // staging row 0..31
    const int sq = tid & 3;          // staging quarter

    const float4 br4 = *(const float4*)&bres[n0 + nloc];

    for (int t = 1; t < TT; t++) {
        // ---- stage x_prev slab (32 rows x 512 cols) as duplicated pairs ----
        const float4* xs = (const float4*)(X + (size_t)(m0 + sr) * TN + (size_t)(t - 1) * NN);
        float* xd = Xsd + 2 * sr;
        #pragma unroll 8
        for (int j = 0; j < 32; j++) {
            int k4 = sq + 4 * j;
            float4 v = __ldcg(xs + k4);
            int k = 4 * k4;
            *(float2*)(xd + (size_t)(k + 0) * RK) = make_float2(v.x, v.x);
            *(float2*)(xd + (size_t)(k + 1) * RK) = make_float2(v.y, v.y);
            *(float2*)(xd + (size_t)(k + 2) * RK) = make_float2(v.z, v.z);
            *(float2*)(xd + (size_t)(k + 3) * RK) = make_float2(v.w, v.w);
        }

        // ---- prefetch epilogue operands (U for this step) ----
        const int r0 = m0 + mloc;
        size_t base = (size_t)r0 * TN + (size_t)t * NN + n0 + nloc;
        float4 u0 = __ldcg((const float4*)&X[base]);
        float4 u1 = __ldcg((const float4*)&X[base + TN]);

        __syncthreads();

        // ---- warp-tiled GEMM ----
        ull a00 = 0, a01 = 0, a10 = 0, a11 = 0;
        const float* xr = Xsd + 2 * mloc;     // word 2m
        const float* wp = Ws + nloc;
        #pragma unroll 8
        for (int k = 0; k < NN; k++) {
            ulonglong2 a = *(const ulonglong2*)(xr + (size_t)k * RK);  // (xm,xm,xm1,xm1)
            ulonglong2 b = *(const ulonglong2*)(wp + k * 32);          // (wn..wn+3)
            fma2(a00, a.x, b.x); fma2(a01, a.x, b.y);
            fma2(a10, a.y, b.x); fma2(a11, a.y, b.y);
        }

        // ---- epilogue: x_t = 0.5*x_prev + 0.5*tanh(U + s + b_res) ----
        float2 s0 = unpack2(a00), s1 = unpack2(a01);
        float2 s2 = unpack2(a10), s3 = unpack2(a11);
        const float* xp = Xsd + (size_t)(n0 + nloc) * RK + 2 * mloc;

        float4 o0, o1;
        o0.x = 0.5f * xp[0 * RK]     + 0.5f * tanhf(u0.x + s0.x + br4.x);
        o0.y = 0.5f * xp[1 * RK]     + 0.5f * tanhf(u0.y + s0.y + br4.y);
        o0.z = 0.5f * xp[2 * RK]     + 0.5f * tanhf(u0.z + s1.x + br4.z);
        o0.w = 0.5f * xp[3 * RK]     + 0.5f * tanhf(u0.w + s1.y + br4.w);
        o1.x = 0.5f * xp[0 * RK + 2] + 0.5f * tanhf(u1.x + s2.x + br4.x);
        o1.y = 0.5f * xp[1 * RK + 2] + 0.5f * tanhf(u1.y + s2.y + br4.y);
        o1.z = 0.5f * xp[2 * RK + 2] + 0.5f * tanhf(u1.z + s3.x + br4.z);
        o1.w = 0.5f * xp[3 * RK + 2] + 0.5f * tanhf(u1.w + s3.y + br4.w);

        *(float4*)&X[base]      = o0;
        *(float4*)&X[base + TN] = o1;
        if (t == TT - 1) {
            *(float4*)&xlast[(size_t)r0 * NN + n0 + nloc]       = o0;
            *(float4*)&xlast[(size_t)(r0 + 1) * NN + n0 + nloc] = o1;
        }

        // ---- 16-CTA group barrier (skip after last step) ----
        if (t < TT - 1) {
            __syncthreads();                    // CTA-scope fence: all STGs ordered
            if (tid == 0) {
                atom_add_rel(cnt, 1u);          // cumulative release
                unsigned target = (unsigned)t * GRP_SZ;
                while (ld_acq(cnt) < target) { }
            }
            __syncthreads();
        }
    }
}

extern "C" void kernel_launch(void* const* d_in, const int* in_sizes, int n_in,
                              void* d_out, int out_size)
{
    const float* inp  = (const float*)d_in[0];
    const float* Win  = (const float*)d_in[1];
    const float* bin  = (const float*)d_in[2];
    const float* Wres = (const float*)d_in[3];
    const float* bres = (const float*)d_in[4];

    float* X = (float*)d_out;                       // (B, T, N)
    float* xlast = X + (size_t)BB * TT * NN;        // (B, N)

    const int smem_bytes = (NN * RK + NN * 32) * sizeof(float);  // 204800
    cudaFuncSetAttribute(esn_persist, cudaFuncAttributeMaxDynamicSharedMemorySize, smem_bytes);

    dim3 g1(BB * TT / 32, NN / 32);
    proj_kernel<<<g1, 128>>>(inp, Win, bin, X);

    init_kernel<<<1, NGRP>>>();

    esn_persist<<<NCTA, 128, smem_bytes>>>(X, Wres, bres, xlast);
}